// round 9
// baseline (speedup 1.0000x reference)
#include <cuda_runtime.h>
#include <math.h>

#define NN 100000
#define NE 1600000
#define NG 256
#define DH 128
#define DOUT 8
#define NLAYERS 4

// Scratch (no allocation allowed) — static device globals.
__device__ float g_pooled[(size_t)NN * DH];
__device__ float g_tmp[(size_t)NN * DH];
__device__ int   g_deg[NN];
__device__ int   g_rowptr[NN + 1];
__device__ int   g_cursor[NN];
__device__ int   g_bsums[256];
__device__ int   g_csr_src[NE];
__device__ float g_csr_mask[NE];

// ---------------------------------------------------------------------------
// f32x2 packed helpers (sm_10x packed fp32 pipe)
// ---------------------------------------------------------------------------
__device__ __forceinline__ unsigned long long pk2(float x) {
    unsigned long long r; unsigned int u = __float_as_uint(x);
    asm("mov.b64 %0, {%1, %1};" : "=l"(r) : "r"(u));
    return r;
}
__device__ __forceinline__ unsigned long long fma2(unsigned long long a,
                                                   unsigned long long b,
                                                   unsigned long long c) {
    unsigned long long d;
    asm("fma.rn.f32x2 %0, %1, %2, %3;" : "=l"(d) : "l"(a), "l"(b), "l"(c));
    return d;
}
__device__ __forceinline__ float2 up2(unsigned long long v) {
    unsigned int lo, hi;
    asm("mov.b64 {%0, %1}, %2;" : "=r"(lo), "=r"(hi) : "l"(v));
    return make_float2(__uint_as_float(lo), __uint_as_float(hi));
}

// ---------------------------------------------------------------------------
// Y[N,128] = act(X[N,128] @ W^T + b), W[128,128] row-major (out,in)
// 256 threads; block tile 64 rows x 128 cols.
// Smem: XsT[k][row] (transposed X, 128x64) + Ws[k][j] (transposed W, 128x128).
// Thread (tx=tid&31, ty=tid>>5): cols tx*4..+3, row-pairs ty*8+2p (p=0..3),
// accumulators are f32x2 packed over the row pair.
// ---------------------------------------------------------------------------
template<bool RELU>
__global__ void __launch_bounds__(256, 2)
gemm128(const float* __restrict__ X, const float* __restrict__ W,
        const float* __restrict__ bias, float* __restrict__ Y, int N)
{
    extern __shared__ float smem[];
    float* XsT = smem;                 // 128*64 floats (32KB)
    float* Ws  = smem + 128 * 64;      // 128*128 floats (64KB), Ws[k*128+j]=W[j][k]

    const int tid = threadIdx.x;
    const int tx  = tid & 31;
    const int ty  = tid >> 5;
    const int row0 = blockIdx.x * 64;

    // Fill W transposed: lanes vary j (fast store index) -> conflict-free STS
    for (int i = tid; i < 128 * 32; i += 256) {
        int j  = i & 127;
        int kk = i >> 7;           // 0..31
        float4 w = reinterpret_cast<const float4*>(W)[j * 32 + kk];
        int k4 = kk << 2;
        Ws[(k4 + 0) * 128 + j] = w.x;
        Ws[(k4 + 1) * 128 + j] = w.y;
        Ws[(k4 + 2) * 128 + j] = w.z;
        Ws[(k4 + 3) * 128 + j] = w.w;
    }
    // Fill X transposed: lanes vary r (fast store index) -> conflict-free STS
    for (int i = tid; i < 64 * 32; i += 256) {
        int r  = i & 63;
        int kk = i >> 6;           // 0..31
        int row = row0 + r;
        float4 v = make_float4(0.f, 0.f, 0.f, 0.f);
        if (row < N)
            v = reinterpret_cast<const float4*>(X)[(size_t)row * 32 + kk];
        int k4 = kk << 2;
        XsT[(k4 + 0) * 64 + r] = v.x;
        XsT[(k4 + 1) * 64 + r] = v.y;
        XsT[(k4 + 2) * 64 + r] = v.z;
        XsT[(k4 + 3) * 64 + r] = v.w;
    }
    __syncthreads();

    unsigned long long acc[4][4];
#pragma unroll
    for (int p = 0; p < 4; p++)
#pragma unroll
        for (int c = 0; c < 4; c++) acc[p][c] = 0ull;

    const float4* Ws4 = reinterpret_cast<const float4*>(Ws);
    const unsigned long long* XsT2 =
        reinterpret_cast<const unsigned long long*>(XsT);

#pragma unroll 8
    for (int k = 0; k < 128; k++) {
        float4 b = Ws4[k * 32 + tx];                   // conflict-free LDS.128
        unsigned long long bb0 = pk2(b.x);
        unsigned long long bb1 = pk2(b.y);
        unsigned long long bb2 = pk2(b.z);
        unsigned long long bb3 = pk2(b.w);
        unsigned long long a0 = XsT2[k * 32 + ty * 4 + 0];  // broadcast LDS.64
        unsigned long long a1 = XsT2[k * 32 + ty * 4 + 1];
        unsigned long long a2 = XsT2[k * 32 + ty * 4 + 2];
        unsigned long long a3 = XsT2[k * 32 + ty * 4 + 3];
        acc[0][0] = fma2(a0, bb0, acc[0][0]);
        acc[0][1] = fma2(a0, bb1, acc[0][1]);
        acc[0][2] = fma2(a0, bb2, acc[0][2]);
        acc[0][3] = fma2(a0, bb3, acc[0][3]);
        acc[1][0] = fma2(a1, bb0, acc[1][0]);
        acc[1][1] = fma2(a1, bb1, acc[1][1]);
        acc[1][2] = fma2(a1, bb2, acc[1][2]);
        acc[1][3] = fma2(a1, bb3, acc[1][3]);
        acc[2][0] = fma2(a2, bb0, acc[2][0]);
        acc[2][1] = fma2(a2, bb1, acc[2][1]);
        acc[2][2] = fma2(a2, bb2, acc[2][2]);
        acc[2][3] = fma2(a2, bb3, acc[2][3]);
        acc[3][0] = fma2(a3, bb0, acc[3][0]);
        acc[3][1] = fma2(a3, bb1, acc[3][1]);
        acc[3][2] = fma2(a3, bb2, acc[3][2]);
        acc[3][3] = fma2(a3, bb3, acc[3][3]);
    }

    float4 bb = reinterpret_cast<const float4*>(bias)[tx];
#pragma unroll
    for (int p = 0; p < 4; p++) {
        float2 c0 = up2(acc[p][0]);
        float2 c1 = up2(acc[p][1]);
        float2 c2 = up2(acc[p][2]);
        float2 c3 = up2(acc[p][3]);
        int row = row0 + ty * 8 + 2 * p;
        if (row < N) {
            float4 o = make_float4(c0.x + bb.x, c1.x + bb.y, c2.x + bb.z, c3.x + bb.w);
            if (RELU) { o.x = fmaxf(o.x, 0.f); o.y = fmaxf(o.y, 0.f);
                        o.z = fmaxf(o.z, 0.f); o.w = fmaxf(o.w, 0.f); }
            reinterpret_cast<float4*>(Y)[(size_t)row * 32 + tx] = o;
        }
        if (row + 1 < N) {
            float4 o = make_float4(c0.y + bb.x, c1.y + bb.y, c2.y + bb.z, c3.y + bb.w);
            if (RELU) { o.x = fmaxf(o.x, 0.f); o.y = fmaxf(o.y, 0.f);
                        o.z = fmaxf(o.z, 0.f); o.w = fmaxf(o.w, 0.f); }
            reinterpret_cast<float4*>(Y)[(size_t)(row + 1) * 32 + tx] = o;
        }
    }
}

// ---------------------------------------------------------------------------
// CSR build: degree count -> block scan -> fill
// ---------------------------------------------------------------------------
__global__ void count_deg(const int* __restrict__ ei, int* __restrict__ deg)
{
    int e = blockIdx.x * blockDim.x + threadIdx.x;
    if (e < NE) atomicAdd(&deg[ei[e]], 1);
}

#define SCAN_B 512
__global__ void scan1(const int* __restrict__ deg, int* __restrict__ rowptr,
                      int* __restrict__ bsums)
{
    __shared__ int sh[SCAN_B];
    int tid = threadIdx.x;
    int i = blockIdx.x * SCAN_B + tid;
    int v = (i < NN) ? deg[i] : 0;
    sh[tid] = v;
    __syncthreads();
#pragma unroll
    for (int off = 1; off < SCAN_B; off <<= 1) {
        int t = (tid >= off) ? sh[tid - off] : 0;
        __syncthreads();
        sh[tid] += t;
        __syncthreads();
    }
    if (i < NN) rowptr[i] = sh[tid] - v;      // exclusive within block
    if (tid == SCAN_B - 1) bsums[blockIdx.x] = sh[tid];
}

__global__ void scan2(int* __restrict__ bsums, int nb)
{
    __shared__ int sh[256];
    int tid = threadIdx.x;
    int v = (tid < nb) ? bsums[tid] : 0;
    sh[tid] = v;
    __syncthreads();
#pragma unroll
    for (int off = 1; off < 256; off <<= 1) {
        int t = (tid >= off) ? sh[tid - off] : 0;
        __syncthreads();
        sh[tid] += t;
        __syncthreads();
    }
    if (tid < nb) bsums[tid] = sh[tid] - v;   // exclusive
}

__global__ void scan3(int* __restrict__ rowptr, const int* __restrict__ bsums,
                      int* __restrict__ cursor)
{
    int i = blockIdx.x * SCAN_B + threadIdx.x;
    if (i < NN) {
        int r = rowptr[i] + bsums[blockIdx.x];
        rowptr[i] = r;
        cursor[i] = r;
    }
    if (i == 0) rowptr[NN] = NE;
}

__global__ void fill_csr(const int* __restrict__ ei, const float* __restrict__ mask,
                         int* __restrict__ cursor, int* __restrict__ csr_src,
                         float* __restrict__ csr_mask)
{
    int e = blockIdx.x * blockDim.x + threadIdx.x;
    if (e >= NE) return;
    int dst = ei[e];
    int src = ei[NE + e];
    int p = atomicAdd(&cursor[dst], 1);
    csr_src[p]  = src;
    csr_mask[p] = mask[e];
}

// ---------------------------------------------------------------------------
// pooled[n] = sum_{e in CSR(n)} mask_e * h[src_e] + (1+eps[l]) * h[n]
// One warp per node; lane = float4 chunk of the 128-dim feature.
// ---------------------------------------------------------------------------
__global__ void aggregate(const float* __restrict__ h, const int* __restrict__ rowptr,
                          const int* __restrict__ csr_src, const float* __restrict__ csr_mask,
                          const float* __restrict__ eps, int l, float* __restrict__ pooled)
{
    int g = (blockIdx.x * blockDim.x + threadIdx.x) >> 5;
    int lane = threadIdx.x & 31;
    if (g >= NN) return;
    int beg = rowptr[g];
    int end = rowptr[g + 1];
    const float4* h4 = reinterpret_cast<const float4*>(h);

    float4 acc = make_float4(0.f, 0.f, 0.f, 0.f);
    int j = beg;
    for (; j + 1 < end; j += 2) {
        int   s0 = csr_src[j],   s1 = csr_src[j + 1];
        float m0 = csr_mask[j],  m1 = csr_mask[j + 1];
        float4 v0 = h4[(size_t)s0 * 32 + lane];
        float4 v1 = h4[(size_t)s1 * 32 + lane];
        acc.x += m0 * v0.x + m1 * v1.x;
        acc.y += m0 * v0.y + m1 * v1.y;
        acc.z += m0 * v0.z + m1 * v1.z;
        acc.w += m0 * v0.w + m1 * v1.w;
    }
    if (j < end) {
        int s0 = csr_src[j];
        float m0 = csr_mask[j];
        float4 v0 = h4[(size_t)s0 * 32 + lane];
        acc.x += m0 * v0.x; acc.y += m0 * v0.y;
        acc.z += m0 * v0.z; acc.w += m0 * v0.w;
    }
    float s = 1.f + eps[l];
    float4 hv = h4[(size_t)g * 32 + lane];
    acc.x += s * hv.x; acc.y += s * hv.y;
    acc.z += s * hv.z; acc.w += s * hv.w;
    reinterpret_cast<float4*>(pooled)[(size_t)g * 32 + lane] = acc;
}

// pooled_sum[g] += sum over 5 embeds of nodes in graph g (batch is sorted)
__global__ void pool_batch(const float* __restrict__ embs, const int* __restrict__ batch,
                           float* __restrict__ ps)
{
    const int j = threadIdx.x;                 // column 0..127
    const int start = blockIdx.x * 128;
    int end = start + 128;
    if (end > NN) end = NN;
    if (start >= NN) return;

    const size_t EMB = (size_t)NN * DH;
    int gc = batch[start];
    float acc = 0.f;
    for (int i = start; i < end; i++) {
        int g = batch[i];
        if (g != gc) {
            atomicAdd(&ps[(size_t)gc * 128 + j], acc);
            acc = 0.f;
            gc = g;
        }
        size_t off = (size_t)i * 128 + j;
        float s = embs[off] + embs[EMB + off] + embs[2 * EMB + off]
                + embs[3 * EMB + off] + embs[4 * EMB + off];
        acc += s;
    }
    atomicAdd(&ps[(size_t)gc * 128 + j], acc);
}

// Head: lin1 = relu(ps @ W1^T + b1); lin1d = lin1; lin2 = lin1 @ W2^T + b2; softmax
__global__ void head(const float* __restrict__ ps,
                     const float* __restrict__ W1, const float* __restrict__ b1,
                     const float* __restrict__ W2, const float* __restrict__ b2,
                     float* __restrict__ lin1, float* __restrict__ lin1d,
                     float* __restrict__ lin2, float* __restrict__ soft)
{
    __shared__ float row[128];
    __shared__ float l1s[128];
    __shared__ float l2s[8];
    const int g = blockIdx.x;
    const int j = threadIdx.x;

    row[j] = ps[(size_t)g * 128 + j];
    __syncthreads();

    float a = b1[j];
#pragma unroll 8
    for (int k = 0; k < 128; k++) a += row[k] * W1[j * 128 + k];
    a = fmaxf(a, 0.f);
    l1s[j] = a;
    lin1[(size_t)g * 128 + j] = a;
    lin1d[(size_t)g * 128 + j] = a;
    __syncthreads();

    if (j < 8) {
        float s = b2[j];
#pragma unroll 8
        for (int k = 0; k < 128; k++) s += l1s[k] * W2[j * 128 + k];
        lin2[(size_t)g * 8 + j] = s;
        l2s[j] = s;
    }
    __syncthreads();
    if (j == 0) {
        float mx = l2s[0];
#pragma unroll
        for (int q = 1; q < 8; q++) mx = fmaxf(mx, l2s[q]);
        float ex[8]; float sum = 0.f;
#pragma unroll
        for (int q = 0; q < 8; q++) { ex[q] = expf(l2s[q] - mx); sum += ex[q]; }
        float inv = 1.f / sum;
#pragma unroll
        for (int q = 0; q < 8; q++) soft[(size_t)g * 8 + q] = ex[q] * inv;
    }
}

extern "C" void kernel_launch(void* const* d_in, const int* in_sizes, int n_in,
                              void* d_out, int out_size)
{
    const float* x     = (const float*)d_in[0];
    const int*   ei    = (const int*)  d_in[1];
    const float* mask  = (const float*)d_in[2];
    const int*   batch = (const int*)  d_in[3];
    const float* eps   = (const float*)d_in[4];
    const float* Wf    = (const float*)d_in[5];
    const float* bf    = (const float*)d_in[6];
    const float* gW    = (const float*)d_in[7];   // [4][2][128][128]
    const float* gb    = (const float*)d_in[8];   // [4][2][128]
    const float* W1    = (const float*)d_in[9];
    const float* b1    = (const float*)d_in[10];
    const float* W2    = (const float*)d_in[11];
    const float* b2    = (const float*)d_in[12];

    float* out  = (float*)d_out;
    const size_t EMB = (size_t)NN * DH;
    float* embs = out;                       // [5][NN][128]
    float* ps   = out + 5 * EMB;             // [256][128]
    float* l1   = ps + (size_t)NG * DH;
    float* l1d  = l1 + (size_t)NG * DH;
    float* l2   = l1d + (size_t)NG * DH;
    float* sm   = l2 + (size_t)NG * DOUT;

    float *pooled = nullptr, *tmp = nullptr, *csr_mask = nullptr;
    int *deg = nullptr, *rowptr = nullptr, *cursor = nullptr, *bsums = nullptr, *csr_src = nullptr;
    cudaGetSymbolAddress((void**)&pooled,   g_pooled);
    cudaGetSymbolAddress((void**)&tmp,      g_tmp);
    cudaGetSymbolAddress((void**)&deg,      g_deg);
    cudaGetSymbolAddress((void**)&rowptr,   g_rowptr);
    cudaGetSymbolAddress((void**)&cursor,   g_cursor);
    cudaGetSymbolAddress((void**)&bsums,    g_bsums);
    cudaGetSymbolAddress((void**)&csr_src,  g_csr_src);
    cudaGetSymbolAddress((void**)&csr_mask, g_csr_mask);

    const int SMEM = (128 * 64 + 128 * 128) * (int)sizeof(float);  // 96 KB
    cudaFuncSetAttribute(gemm128<false>, cudaFuncAttributeMaxDynamicSharedMemorySize, SMEM);
    cudaFuncSetAttribute(gemm128<true>,  cudaFuncAttributeMaxDynamicSharedMemorySize, SMEM);

    const int GEMM_BLOCKS = (NN + 63) / 64;       // 1563
    const int SCAN_BLOCKS = (NN + SCAN_B - 1) / SCAN_B;  // 196
    const int EDGE_BLOCKS = (NE + 255) / 256;
    const int AGG_BLOCKS  = (NN * 32 + 255) / 256;
    const int POOL_BLOCKS = (NN + 127) / 128;

    // zero pooled_sum region (d_out is poisoned) + degree histogram
    cudaMemsetAsync(ps, 0, (size_t)NG * DH * sizeof(float), 0);
    cudaMemsetAsync(deg, 0, (size_t)NN * sizeof(int), 0);

    // CSR build (reused across all 4 layers)
    count_deg<<<EDGE_BLOCKS, 256>>>(ei, deg);
    scan1<<<SCAN_BLOCKS, SCAN_B>>>(deg, rowptr, bsums);
    scan2<<<1, 256>>>(bsums, SCAN_BLOCKS);
    scan3<<<SCAN_BLOCKS, SCAN_B>>>(rowptr, bsums, cursor);
    fill_csr<<<EDGE_BLOCKS, 256>>>(ei, mask, cursor, csr_src, csr_mask);

    // first linear (NO relu)
    gemm128<false><<<GEMM_BLOCKS, 256, SMEM>>>(x, Wf, bf, embs, NN);

    for (int l = 0; l < NLAYERS; l++) {
        const float* h = embs + (size_t)l * EMB;
        aggregate<<<AGG_BLOCKS, 256>>>(h, rowptr, csr_src, csr_mask, eps, l, pooled);
        gemm128<true><<<GEMM_BLOCKS, 256, SMEM>>>(
            pooled, gW + (size_t)(l * 2 + 0) * 128 * 128, gb + (size_t)(l * 2 + 0) * 128,
            tmp, NN);
        gemm128<true><<<GEMM_BLOCKS, 256, SMEM>>>(
            tmp, gW + (size_t)(l * 2 + 1) * 128 * 128, gb + (size_t)(l * 2 + 1) * 128,
            embs + (size_t)(l + 1) * EMB, NN);
    }

    pool_batch<<<POOL_BLOCKS, 128>>>(embs, batch, ps);
    head<<<NG, 128>>>(ps, W1, b1, W2, b2, l1, l1d, l2, sm);
}

// round 10
// speedup vs baseline: 1.0069x; 1.0069x over previous
#include <cuda_runtime.h>
#include <math.h>

#define NN 100000
#define NE 1600000
#define NG 256
#define DH 128
#define DOUT 8
#define NLAYERS 4

// Scratch (no allocation allowed) — static device globals.
__device__ float g_pooled[(size_t)NN * DH];
__device__ float g_tmp[(size_t)NN * DH];
__device__ int   g_deg[NN];
__device__ int   g_rowptr[NN + 1];
__device__ int   g_cursor[NN];
__device__ int   g_bsums[256];
__device__ int   g_csr_src[NE];
__device__ float g_csr_mask[NE];

// ---------------------------------------------------------------------------
// f32x2 packed helpers (sm_10x packed fp32 pipe)
// ---------------------------------------------------------------------------
__device__ __forceinline__ unsigned long long pk2(float x) {
    unsigned long long r; unsigned int u = __float_as_uint(x);
    asm("mov.b64 %0, {%1, %1};" : "=l"(r) : "r"(u));
    return r;
}
__device__ __forceinline__ unsigned long long fma2(unsigned long long a,
                                                   unsigned long long b,
                                                   unsigned long long c) {
    unsigned long long d;
    asm("fma.rn.f32x2 %0, %1, %2, %3;" : "=l"(d) : "l"(a), "l"(b), "l"(c));
    return d;
}
__device__ __forceinline__ float2 up2(unsigned long long v) {
    unsigned int lo, hi;
    asm("mov.b64 {%0, %1}, %2;" : "=r"(lo), "=r"(hi) : "l"(v));
    return make_float2(__uint_as_float(lo), __uint_as_float(hi));
}

// ---------------------------------------------------------------------------
// Y[N,128] = act(X[N,128] @ W^T + b), W[128,128] row-major (out,in)
// 256 threads; block tile 64 rows x 128 cols.
// Smem: XsT[k][row] (transposed X, 128x64) + Ws[k][j] (transposed W, 128x128).
// Thread (tx=tid&31, ty=tid>>5): cols tx*4..+3, row-pairs ty*8+2p (p=0..3),
// accumulators are f32x2 packed over the row pair.
// ---------------------------------------------------------------------------
template<bool RELU>
__global__ void __launch_bounds__(256, 2)
gemm128(const float* __restrict__ X, const float* __restrict__ W,
        const float* __restrict__ bias, float* __restrict__ Y, int N)
{
    extern __shared__ float smem[];
    float* XsT = smem;                 // 128*64 floats (32KB)
    float* Ws  = smem + 128 * 64;      // 128*128 floats (64KB), Ws[k*128+j]=W[j][k]

    const int tid = threadIdx.x;
    const int tx  = tid & 31;
    const int ty  = tid >> 5;
    const int row0 = blockIdx.x * 64;

    // Fill W transposed: lanes vary j (fast store index) -> conflict-free STS
    for (int i = tid; i < 128 * 32; i += 256) {
        int j  = i & 127;
        int kk = i >> 7;           // 0..31
        float4 w = reinterpret_cast<const float4*>(W)[j * 32 + kk];
        int k4 = kk << 2;
        Ws[(k4 + 0) * 128 + j] = w.x;
        Ws[(k4 + 1) * 128 + j] = w.y;
        Ws[(k4 + 2) * 128 + j] = w.z;
        Ws[(k4 + 3) * 128 + j] = w.w;
    }
    // Fill X transposed: lanes vary r (fast store index) -> conflict-free STS
    for (int i = tid; i < 64 * 32; i += 256) {
        int r  = i & 63;
        int kk = i >> 6;           // 0..31
        int row = row0 + r;
        float4 v = make_float4(0.f, 0.f, 0.f, 0.f);
        if (row < N)
            v = reinterpret_cast<const float4*>(X)[(size_t)row * 32 + kk];
        int k4 = kk << 2;
        XsT[(k4 + 0) * 64 + r] = v.x;
        XsT[(k4 + 1) * 64 + r] = v.y;
        XsT[(k4 + 2) * 64 + r] = v.z;
        XsT[(k4 + 3) * 64 + r] = v.w;
    }
    __syncthreads();

    unsigned long long acc[4][4];
#pragma unroll
    for (int p = 0; p < 4; p++)
#pragma unroll
        for (int c = 0; c < 4; c++) acc[p][c] = 0ull;

    const float4* Ws4 = reinterpret_cast<const float4*>(Ws);
    const unsigned long long* XsT2 =
        reinterpret_cast<const unsigned long long*>(XsT);

#pragma unroll 8
    for (int k = 0; k < 128; k++) {
        float4 b = Ws4[k * 32 + tx];                   // conflict-free LDS.128
        unsigned long long bb0 = pk2(b.x);
        unsigned long long bb1 = pk2(b.y);
        unsigned long long bb2 = pk2(b.z);
        unsigned long long bb3 = pk2(b.w);
        unsigned long long a0 = XsT2[k * 32 + ty * 4 + 0];  // broadcast LDS.64
        unsigned long long a1 = XsT2[k * 32 + ty * 4 + 1];
        unsigned long long a2 = XsT2[k * 32 + ty * 4 + 2];
        unsigned long long a3 = XsT2[k * 32 + ty * 4 + 3];
        acc[0][0] = fma2(a0, bb0, acc[0][0]);
        acc[0][1] = fma2(a0, bb1, acc[0][1]);
        acc[0][2] = fma2(a0, bb2, acc[0][2]);
        acc[0][3] = fma2(a0, bb3, acc[0][3]);
        acc[1][0] = fma2(a1, bb0, acc[1][0]);
        acc[1][1] = fma2(a1, bb1, acc[1][1]);
        acc[1][2] = fma2(a1, bb2, acc[1][2]);
        acc[1][3] = fma2(a1, bb3, acc[1][3]);
        acc[2][0] = fma2(a2, bb0, acc[2][0]);
        acc[2][1] = fma2(a2, bb1, acc[2][1]);
        acc[2][2] = fma2(a2, bb2, acc[2][2]);
        acc[2][3] = fma2(a2, bb3, acc[2][3]);
        acc[3][0] = fma2(a3, bb0, acc[3][0]);
        acc[3][1] = fma2(a3, bb1, acc[3][1]);
        acc[3][2] = fma2(a3, bb2, acc[3][2]);
        acc[3][3] = fma2(a3, bb3, acc[3][3]);
    }

    float4 bb = reinterpret_cast<const float4*>(bias)[tx];
#pragma unroll
    for (int p = 0; p < 4; p++) {
        float2 c0 = up2(acc[p][0]);
        float2 c1 = up2(acc[p][1]);
        float2 c2 = up2(acc[p][2]);
        float2 c3 = up2(acc[p][3]);
        int row = row0 + ty * 8 + 2 * p;
        if (row < N) {
            float4 o = make_float4(c0.x + bb.x, c1.x + bb.y, c2.x + bb.z, c3.x + bb.w);
            if (RELU) { o.x = fmaxf(o.x, 0.f); o.y = fmaxf(o.y, 0.f);
                        o.z = fmaxf(o.z, 0.f); o.w = fmaxf(o.w, 0.f); }
            reinterpret_cast<float4*>(Y)[(size_t)row * 32 + tx] = o;
        }
        if (row + 1 < N) {
            float4 o = make_float4(c0.y + bb.x, c1.y + bb.y, c2.y + bb.z, c3.y + bb.w);
            if (RELU) { o.x = fmaxf(o.x, 0.f); o.y = fmaxf(o.y, 0.f);
                        o.z = fmaxf(o.z, 0.f); o.w = fmaxf(o.w, 0.f); }
            reinterpret_cast<float4*>(Y)[(size_t)(row + 1) * 32 + tx] = o;
        }
    }
}

// ---------------------------------------------------------------------------
// CSR build: degree count -> block scan -> fill
// ---------------------------------------------------------------------------
__global__ void count_deg(const int* __restrict__ ei, int* __restrict__ deg)
{
    int e = blockIdx.x * blockDim.x + threadIdx.x;
    if (e < NE) atomicAdd(&deg[ei[e]], 1);
}

#define SCAN_B 512
__global__ void scan1(const int* __restrict__ deg, int* __restrict__ rowptr,
                      int* __restrict__ bsums)
{
    __shared__ int sh[SCAN_B];
    int tid = threadIdx.x;
    int i = blockIdx.x * SCAN_B + tid;
    int v = (i < NN) ? deg[i] : 0;
    sh[tid] = v;
    __syncthreads();
#pragma unroll
    for (int off = 1; off < SCAN_B; off <<= 1) {
        int t = (tid >= off) ? sh[tid - off] : 0;
        __syncthreads();
        sh[tid] += t;
        __syncthreads();
    }
    if (i < NN) rowptr[i] = sh[tid] - v;      // exclusive within block
    if (tid == SCAN_B - 1) bsums[blockIdx.x] = sh[tid];
}

__global__ void scan2(int* __restrict__ bsums, int nb)
{
    __shared__ int sh[256];
    int tid = threadIdx.x;
    int v = (tid < nb) ? bsums[tid] : 0;
    sh[tid] = v;
    __syncthreads();
#pragma unroll
    for (int off = 1; off < 256; off <<= 1) {
        int t = (tid >= off) ? sh[tid - off] : 0;
        __syncthreads();
        sh[tid] += t;
        __syncthreads();
    }
    if (tid < nb) bsums[tid] = sh[tid] - v;   // exclusive
}

__global__ void scan3(int* __restrict__ rowptr, const int* __restrict__ bsums,
                      int* __restrict__ cursor)
{
    int i = blockIdx.x * SCAN_B + threadIdx.x;
    if (i < NN) {
        int r = rowptr[i] + bsums[blockIdx.x];
        rowptr[i] = r;
        cursor[i] = r;
    }
    if (i == 0) rowptr[NN] = NE;
}

__global__ void fill_csr(const int* __restrict__ ei, const float* __restrict__ mask,
                         int* __restrict__ cursor, int* __restrict__ csr_src,
                         float* __restrict__ csr_mask)
{
    int e = blockIdx.x * blockDim.x + threadIdx.x;
    if (e >= NE) return;
    int dst = ei[e];
    int src = ei[NE + e];
    int p = atomicAdd(&cursor[dst], 1);
    csr_src[p]  = src;
    csr_mask[p] = mask[e];
}

// ---------------------------------------------------------------------------
// pooled[n] = sum_{e in CSR(n)} mask_e * h[src_e] + (1+eps[l]) * h[n]
// One warp per node; lane = float4 chunk of the 128-dim feature.
// ---------------------------------------------------------------------------
__global__ void aggregate(const float* __restrict__ h, const int* __restrict__ rowptr,
                          const int* __restrict__ csr_src, const float* __restrict__ csr_mask,
                          const float* __restrict__ eps, int l, float* __restrict__ pooled)
{
    int g = (blockIdx.x * blockDim.x + threadIdx.x) >> 5;
    int lane = threadIdx.x & 31;
    if (g >= NN) return;
    int beg = rowptr[g];
    int end = rowptr[g + 1];
    const float4* h4 = reinterpret_cast<const float4*>(h);

    float4 acc = make_float4(0.f, 0.f, 0.f, 0.f);
    int j = beg;
    for (; j + 1 < end; j += 2) {
        int   s0 = csr_src[j],   s1 = csr_src[j + 1];
        float m0 = csr_mask[j],  m1 = csr_mask[j + 1];
        float4 v0 = h4[(size_t)s0 * 32 + lane];
        float4 v1 = h4[(size_t)s1 * 32 + lane];
        acc.x += m0 * v0.x + m1 * v1.x;
        acc.y += m0 * v0.y + m1 * v1.y;
        acc.z += m0 * v0.z + m1 * v1.z;
        acc.w += m0 * v0.w + m1 * v1.w;
    }
    if (j < end) {
        int s0 = csr_src[j];
        float m0 = csr_mask[j];
        float4 v0 = h4[(size_t)s0 * 32 + lane];
        acc.x += m0 * v0.x; acc.y += m0 * v0.y;
        acc.z += m0 * v0.z; acc.w += m0 * v0.w;
    }
    float s = 1.f + eps[l];
    float4 hv = h4[(size_t)g * 32 + lane];
    acc.x += s * hv.x; acc.y += s * hv.y;
    acc.z += s * hv.z; acc.w += s * hv.w;
    reinterpret_cast<float4*>(pooled)[(size_t)g * 32 + lane] = acc;
}

// pooled_sum[g] += sum over 5 embeds of nodes in graph g (batch is sorted)
__global__ void pool_batch(const float* __restrict__ embs, const int* __restrict__ batch,
                           float* __restrict__ ps)
{
    const int j = threadIdx.x;                 // column 0..127
    const int start = blockIdx.x * 128;
    int end = start + 128;
    if (end > NN) end = NN;
    if (start >= NN) return;

    const size_t EMB = (size_t)NN * DH;
    int gc = batch[start];
    float acc = 0.f;
    for (int i = start; i < end; i++) {
        int g = batch[i];
        if (g != gc) {
            atomicAdd(&ps[(size_t)gc * 128 + j], acc);
            acc = 0.f;
            gc = g;
        }
        size_t off = (size_t)i * 128 + j;
        float s = embs[off] + embs[EMB + off] + embs[2 * EMB + off]
                + embs[3 * EMB + off] + embs[4 * EMB + off];
        acc += s;
    }
    atomicAdd(&ps[(size_t)gc * 128 + j], acc);
}

// Head: lin1 = relu(ps @ W1^T + b1); lin1d = lin1; lin2 = lin1 @ W2^T + b2; softmax
__global__ void head(const float* __restrict__ ps,
                     const float* __restrict__ W1, const float* __restrict__ b1,
                     const float* __restrict__ W2, const float* __restrict__ b2,
                     float* __restrict__ lin1, float* __restrict__ lin1d,
                     float* __restrict__ lin2, float* __restrict__ soft)
{
    __shared__ float row[128];
    __shared__ float l1s[128];
    __shared__ float l2s[8];
    const int g = blockIdx.x;
    const int j = threadIdx.x;

    row[j] = ps[(size_t)g * 128 + j];
    __syncthreads();

    float a = b1[j];
#pragma unroll 8
    for (int k = 0; k < 128; k++) a += row[k] * W1[j * 128 + k];
    a = fmaxf(a, 0.f);
    l1s[j] = a;
    lin1[(size_t)g * 128 + j] = a;
    lin1d[(size_t)g * 128 + j] = a;
    __syncthreads();

    if (j < 8) {
        float s = b2[j];
#pragma unroll 8
        for (int k = 0; k < 128; k++) s += l1s[k] * W2[j * 128 + k];
        lin2[(size_t)g * 8 + j] = s;
        l2s[j] = s;
    }
    __syncthreads();
    if (j == 0) {
        float mx = l2s[0];
#pragma unroll
        for (int q = 1; q < 8; q++) mx = fmaxf(mx, l2s[q]);
        float ex[8]; float sum = 0.f;
#pragma unroll
        for (int q = 0; q < 8; q++) { ex[q] = expf(l2s[q] - mx); sum += ex[q]; }
        float inv = 1.f / sum;
#pragma unroll
        for (int q = 0; q < 8; q++) soft[(size_t)g * 8 + q] = ex[q] * inv;
    }
}

extern "C" void kernel_launch(void* const* d_in, const int* in_sizes, int n_in,
                              void* d_out, int out_size)
{
    const float* x     = (const float*)d_in[0];
    const int*   ei    = (const int*)  d_in[1];
    const float* mask  = (const float*)d_in[2];
    const int*   batch = (const int*)  d_in[3];
    const float* eps   = (const float*)d_in[4];
    const float* Wf    = (const float*)d_in[5];
    const float* bf    = (const float*)d_in[6];
    const float* gW    = (const float*)d_in[7];   // [4][2][128][128]
    const float* gb    = (const float*)d_in[8];   // [4][2][128]
    const float* W1    = (const float*)d_in[9];
    const float* b1    = (const float*)d_in[10];
    const float* W2    = (const float*)d_in[11];
    const float* b2    = (const float*)d_in[12];

    float* out  = (float*)d_out;
    const size_t EMB = (size_t)NN * DH;
    float* embs = out;                       // [5][NN][128]
    float* ps   = out + 5 * EMB;             // [256][128]
    float* l1   = ps + (size_t)NG * DH;
    float* l1d  = l1 + (size_t)NG * DH;
    float* l2   = l1d + (size_t)NG * DH;
    float* sm   = l2 + (size_t)NG * DOUT;

    float *pooled = nullptr, *tmp = nullptr, *csr_mask = nullptr;
    int *deg = nullptr, *rowptr = nullptr, *cursor = nullptr, *bsums = nullptr, *csr_src = nullptr;
    cudaGetSymbolAddress((void**)&pooled,   g_pooled);
    cudaGetSymbolAddress((void**)&tmp,      g_tmp);
    cudaGetSymbolAddress((void**)&deg,      g_deg);
    cudaGetSymbolAddress((void**)&rowptr,   g_rowptr);
    cudaGetSymbolAddress((void**)&cursor,   g_cursor);
    cudaGetSymbolAddress((void**)&bsums,    g_bsums);
    cudaGetSymbolAddress((void**)&csr_src,  g_csr_src);
    cudaGetSymbolAddress((void**)&csr_mask, g_csr_mask);

    const int SMEM = (128 * 64 + 128 * 128) * (int)sizeof(float);  // 96 KB
    cudaFuncSetAttribute(gemm128<false>, cudaFuncAttributeMaxDynamicSharedMemorySize, SMEM);
    cudaFuncSetAttribute(gemm128<true>,  cudaFuncAttributeMaxDynamicSharedMemorySize, SMEM);

    const int GEMM_BLOCKS = (NN + 63) / 64;       // 1563
    const int SCAN_BLOCKS = (NN + SCAN_B - 1) / SCAN_B;  // 196
    const int EDGE_BLOCKS = (NE + 255) / 256;
    const int AGG_BLOCKS  = (NN * 32 + 255) / 256;
    const int POOL_BLOCKS = (NN + 127) / 128;

    // zero pooled_sum region (d_out is poisoned) + degree histogram
    cudaMemsetAsync(ps, 0, (size_t)NG * DH * sizeof(float), 0);
    cudaMemsetAsync(deg, 0, (size_t)NN * sizeof(int), 0);

    // CSR build (reused across all 4 layers)
    count_deg<<<EDGE_BLOCKS, 256>>>(ei, deg);
    scan1<<<SCAN_BLOCKS, SCAN_B>>>(deg, rowptr, bsums);
    scan2<<<1, 256>>>(bsums, SCAN_BLOCKS);
    scan3<<<SCAN_BLOCKS, SCAN_B>>>(rowptr, bsums, cursor);
    fill_csr<<<EDGE_BLOCKS, 256>>>(ei, mask, cursor, csr_src, csr_mask);

    // first linear (NO relu)
    gemm128<false><<<GEMM_BLOCKS, 256, SMEM>>>(x, Wf, bf, embs, NN);

    for (int l = 0; l < NLAYERS; l++) {
        const float* h = embs + (size_t)l * EMB;
        aggregate<<<AGG_BLOCKS, 256>>>(h, rowptr, csr_src, csr_mask, eps, l, pooled);
        gemm128<true><<<GEMM_BLOCKS, 256, SMEM>>>(
            pooled, gW + (size_t)(l * 2 + 0) * 128 * 128, gb + (size_t)(l * 2 + 0) * 128,
            tmp, NN);
        gemm128<true><<<GEMM_BLOCKS, 256, SMEM>>>(
            tmp, gW + (size_t)(l * 2 + 1) * 128 * 128, gb + (size_t)(l * 2 + 1) * 128,
            embs + (size_t)(l + 1) * EMB, NN);
    }

    pool_batch<<<POOL_BLOCKS, 128>>>(embs, batch, ps);
    head<<<NG, 128>>>(ps, W1, b1, W2, b2, l1, l1d, l2, sm);
}

// round 11
// speedup vs baseline: 1.0076x; 1.0007x over previous
#include <cuda_runtime.h>
#include <math.h>

#define NN 100000
#define NE 1600000
#define NG 256
#define DH 128
#define DOUT 8
#define NLAYERS 4

// Scratch (no allocation allowed) — static device globals.
__device__ float g_pooled[(size_t)NN * DH];
__device__ float g_tmp[(size_t)NN * DH];
__device__ int   g_deg[NN];
__device__ int   g_rowptr[NN + 1];
__device__ int   g_cursor[NN];
__device__ int   g_bsums[256];
__device__ int   g_csr_src[NE];
__device__ float g_csr_mask[NE];

// ---------------------------------------------------------------------------
// f32x2 packed helpers (sm_10x packed fp32 pipe)
// ---------------------------------------------------------------------------
__device__ __forceinline__ unsigned long long pk2(float x) {
    unsigned long long r; unsigned int u = __float_as_uint(x);
    asm("mov.b64 %0, {%1, %1};" : "=l"(r) : "r"(u));
    return r;
}
__device__ __forceinline__ unsigned long long fma2(unsigned long long a,
                                                   unsigned long long b,
                                                   unsigned long long c) {
    unsigned long long d;
    asm("fma.rn.f32x2 %0, %1, %2, %3;" : "=l"(d) : "l"(a), "l"(b), "l"(c));
    return d;
}
__device__ __forceinline__ float2 up2(unsigned long long v) {
    unsigned int lo, hi;
    asm("mov.b64 {%0, %1}, %2;" : "=r"(lo), "=r"(hi) : "l"(v));
    return make_float2(__uint_as_float(lo), __uint_as_float(hi));
}

// ---------------------------------------------------------------------------
// Y[N,128] = act(X[N,128] @ W^T + b), W[128,128] row-major (out,in)
// 256 threads; block tile 64 rows x 128 cols.
// Smem: XsT[k][row] (transposed X, 128x64) + Ws[k][j] (transposed W, 128x128).
// Thread (tx=tid&31, ty=tid>>5): cols tx*4..+3, row-pairs ty*8+2p (p=0..3),
// accumulators are f32x2 packed over the row pair.
// ---------------------------------------------------------------------------
template<bool RELU>
__global__ void __launch_bounds__(256, 2)
gemm128(const float* __restrict__ X, const float* __restrict__ W,
        const float* __restrict__ bias, float* __restrict__ Y, int N)
{
    extern __shared__ float smem[];
    float* XsT = smem;                 // 128*64 floats (32KB)
    float* Ws  = smem + 128 * 64;      // 128*128 floats (64KB), Ws[k*128+j]=W[j][k]

    const int tid = threadIdx.x;
    const int tx  = tid & 31;
    const int ty  = tid >> 5;
    const int row0 = blockIdx.x * 64;

    // Fill W transposed: lanes vary j (fast store index) -> conflict-free STS
    for (int i = tid; i < 128 * 32; i += 256) {
        int j  = i & 127;
        int kk = i >> 7;           // 0..31
        float4 w = reinterpret_cast<const float4*>(W)[j * 32 + kk];
        int k4 = kk << 2;
        Ws[(k4 + 0) * 128 + j] = w.x;
        Ws[(k4 + 1) * 128 + j] = w.y;
        Ws[(k4 + 2) * 128 + j] = w.z;
        Ws[(k4 + 3) * 128 + j] = w.w;
    }
    // Fill X transposed: lanes vary r (fast store index) -> conflict-free STS
    for (int i = tid; i < 64 * 32; i += 256) {
        int r  = i & 63;
        int kk = i >> 6;           // 0..31
        int row = row0 + r;
        float4 v = make_float4(0.f, 0.f, 0.f, 0.f);
        if (row < N)
            v = reinterpret_cast<const float4*>(X)[(size_t)row * 32 + kk];
        int k4 = kk << 2;
        XsT[(k4 + 0) * 64 + r] = v.x;
        XsT[(k4 + 1) * 64 + r] = v.y;
        XsT[(k4 + 2) * 64 + r] = v.z;
        XsT[(k4 + 3) * 64 + r] = v.w;
    }
    __syncthreads();

    unsigned long long acc[4][4];
#pragma unroll
    for (int p = 0; p < 4; p++)
#pragma unroll
        for (int c = 0; c < 4; c++) acc[p][c] = 0ull;

    const float4* Ws4 = reinterpret_cast<const float4*>(Ws);
    const unsigned long long* XsT2 =
        reinterpret_cast<const unsigned long long*>(XsT);

#pragma unroll 8
    for (int k = 0; k < 128; k++) {
        float4 b = Ws4[k * 32 + tx];                   // conflict-free LDS.128
        unsigned long long bb0 = pk2(b.x);
        unsigned long long bb1 = pk2(b.y);
        unsigned long long bb2 = pk2(b.z);
        unsigned long long bb3 = pk2(b.w);
        unsigned long long a0 = XsT2[k * 32 + ty * 4 + 0];  // broadcast LDS.64
        unsigned long long a1 = XsT2[k * 32 + ty * 4 + 1];
        unsigned long long a2 = XsT2[k * 32 + ty * 4 + 2];
        unsigned long long a3 = XsT2[k * 32 + ty * 4 + 3];
        acc[0][0] = fma2(a0, bb0, acc[0][0]);
        acc[0][1] = fma2(a0, bb1, acc[0][1]);
        acc[0][2] = fma2(a0, bb2, acc[0][2]);
        acc[0][3] = fma2(a0, bb3, acc[0][3]);
        acc[1][0] = fma2(a1, bb0, acc[1][0]);
        acc[1][1] = fma2(a1, bb1, acc[1][1]);
        acc[1][2] = fma2(a1, bb2, acc[1][2]);
        acc[1][3] = fma2(a1, bb3, acc[1][3]);
        acc[2][0] = fma2(a2, bb0, acc[2][0]);
        acc[2][1] = fma2(a2, bb1, acc[2][1]);
        acc[2][2] = fma2(a2, bb2, acc[2][2]);
        acc[2][3] = fma2(a2, bb3, acc[2][3]);
        acc[3][0] = fma2(a3, bb0, acc[3][0]);
        acc[3][1] = fma2(a3, bb1, acc[3][1]);
        acc[3][2] = fma2(a3, bb2, acc[3][2]);
        acc[3][3] = fma2(a3, bb3, acc[3][3]);
    }

    float4 bb = reinterpret_cast<const float4*>(bias)[tx];
#pragma unroll
    for (int p = 0; p < 4; p++) {
        float2 c0 = up2(acc[p][0]);
        float2 c1 = up2(acc[p][1]);
        float2 c2 = up2(acc[p][2]);
        float2 c3 = up2(acc[p][3]);
        int row = row0 + ty * 8 + 2 * p;
        if (row < N) {
            float4 o = make_float4(c0.x + bb.x, c1.x + bb.y, c2.x + bb.z, c3.x + bb.w);
            if (RELU) { o.x = fmaxf(o.x, 0.f); o.y = fmaxf(o.y, 0.f);
                        o.z = fmaxf(o.z, 0.f); o.w = fmaxf(o.w, 0.f); }
            reinterpret_cast<float4*>(Y)[(size_t)row * 32 + tx] = o;
        }
        if (row + 1 < N) {
            float4 o = make_float4(c0.y + bb.x, c1.y + bb.y, c2.y + bb.z, c3.y + bb.w);
            if (RELU) { o.x = fmaxf(o.x, 0.f); o.y = fmaxf(o.y, 0.f);
                        o.z = fmaxf(o.z, 0.f); o.w = fmaxf(o.w, 0.f); }
            reinterpret_cast<float4*>(Y)[(size_t)(row + 1) * 32 + tx] = o;
        }
    }
}

// ---------------------------------------------------------------------------
// CSR build: degree count -> block scan -> fill
// ---------------------------------------------------------------------------
__global__ void count_deg(const int* __restrict__ ei, int* __restrict__ deg)
{
    int e = blockIdx.x * blockDim.x + threadIdx.x;
    if (e < NE) atomicAdd(&deg[ei[e]], 1);
}

#define SCAN_B 512
__global__ void scan1(const int* __restrict__ deg, int* __restrict__ rowptr,
                      int* __restrict__ bsums)
{
    __shared__ int sh[SCAN_B];
    int tid = threadIdx.x;
    int i = blockIdx.x * SCAN_B + tid;
    int v = (i < NN) ? deg[i] : 0;
    sh[tid] = v;
    __syncthreads();
#pragma unroll
    for (int off = 1; off < SCAN_B; off <<= 1) {
        int t = (tid >= off) ? sh[tid - off] : 0;
        __syncthreads();
        sh[tid] += t;
        __syncthreads();
    }
    if (i < NN) rowptr[i] = sh[tid] - v;      // exclusive within block
    if (tid == SCAN_B - 1) bsums[blockIdx.x] = sh[tid];
}

__global__ void scan2(int* __restrict__ bsums, int nb)
{
    __shared__ int sh[256];
    int tid = threadIdx.x;
    int v = (tid < nb) ? bsums[tid] : 0;
    sh[tid] = v;
    __syncthreads();
#pragma unroll
    for (int off = 1; off < 256; off <<= 1) {
        int t = (tid >= off) ? sh[tid - off] : 0;
        __syncthreads();
        sh[tid] += t;
        __syncthreads();
    }
    if (tid < nb) bsums[tid] = sh[tid] - v;   // exclusive
}

__global__ void scan3(int* __restrict__ rowptr, const int* __restrict__ bsums,
                      int* __restrict__ cursor)
{
    int i = blockIdx.x * SCAN_B + threadIdx.x;
    if (i < NN) {
        int r = rowptr[i] + bsums[blockIdx.x];
        rowptr[i] = r;
        cursor[i] = r;
    }
    if (i == 0) rowptr[NN] = NE;
}

__global__ void fill_csr(const int* __restrict__ ei, const float* __restrict__ mask,
                         int* __restrict__ cursor, int* __restrict__ csr_src,
                         float* __restrict__ csr_mask)
{
    int e = blockIdx.x * blockDim.x + threadIdx.x;
    if (e >= NE) return;
    int dst = ei[e];
    int src = ei[NE + e];
    int p = atomicAdd(&cursor[dst], 1);
    csr_src[p]  = src;
    csr_mask[p] = mask[e];
}

// ---------------------------------------------------------------------------
// pooled[n] = sum_{e in CSR(n)} mask_e * h[src_e] + (1+eps[l]) * h[n]
// One warp per node; lane = float4 chunk of the 128-dim feature.
// ---------------------------------------------------------------------------
__global__ void aggregate(const float* __restrict__ h, const int* __restrict__ rowptr,
                          const int* __restrict__ csr_src, const float* __restrict__ csr_mask,
                          const float* __restrict__ eps, int l, float* __restrict__ pooled)
{
    int g = (blockIdx.x * blockDim.x + threadIdx.x) >> 5;
    int lane = threadIdx.x & 31;
    if (g >= NN) return;
    int beg = rowptr[g];
    int end = rowptr[g + 1];
    const float4* h4 = reinterpret_cast<const float4*>(h);

    float4 acc = make_float4(0.f, 0.f, 0.f, 0.f);
    int j = beg;
    for (; j + 1 < end; j += 2) {
        int   s0 = csr_src[j],   s1 = csr_src[j + 1];
        float m0 = csr_mask[j],  m1 = csr_mask[j + 1];
        float4 v0 = h4[(size_t)s0 * 32 + lane];
        float4 v1 = h4[(size_t)s1 * 32 + lane];
        acc.x += m0 * v0.x + m1 * v1.x;
        acc.y += m0 * v0.y + m1 * v1.y;
        acc.z += m0 * v0.z + m1 * v1.z;
        acc.w += m0 * v0.w + m1 * v1.w;
    }
    if (j < end) {
        int s0 = csr_src[j];
        float m0 = csr_mask[j];
        float4 v0 = h4[(size_t)s0 * 32 + lane];
        acc.x += m0 * v0.x; acc.y += m0 * v0.y;
        acc.z += m0 * v0.z; acc.w += m0 * v0.w;
    }
    float s = 1.f + eps[l];
    float4 hv = h4[(size_t)g * 32 + lane];
    acc.x += s * hv.x; acc.y += s * hv.y;
    acc.z += s * hv.z; acc.w += s * hv.w;
    reinterpret_cast<float4*>(pooled)[(size_t)g * 32 + lane] = acc;
}

// pooled_sum[g] += sum over 5 embeds of nodes in graph g (batch is sorted)
__global__ void pool_batch(const float* __restrict__ embs, const int* __restrict__ batch,
                           float* __restrict__ ps)
{
    const int j = threadIdx.x;                 // column 0..127
    const int start = blockIdx.x * 128;
    int end = start + 128;
    if (end > NN) end = NN;
    if (start >= NN) return;

    const size_t EMB = (size_t)NN * DH;
    int gc = batch[start];
    float acc = 0.f;
    for (int i = start; i < end; i++) {
        int g = batch[i];
        if (g != gc) {
            atomicAdd(&ps[(size_t)gc * 128 + j], acc);
            acc = 0.f;
            gc = g;
        }
        size_t off = (size_t)i * 128 + j;
        float s = embs[off] + embs[EMB + off] + embs[2 * EMB + off]
                + embs[3 * EMB + off] + embs[4 * EMB + off];
        acc += s;
    }
    atomicAdd(&ps[(size_t)gc * 128 + j], acc);
}

// Head: lin1 = relu(ps @ W1^T + b1); lin1d = lin1; lin2 = lin1 @ W2^T + b2; softmax
__global__ void head(const float* __restrict__ ps,
                     const float* __restrict__ W1, const float* __restrict__ b1,
                     const float* __restrict__ W2, const float* __restrict__ b2,
                     float* __restrict__ lin1, float* __restrict__ lin1d,
                     float* __restrict__ lin2, float* __restrict__ soft)
{
    __shared__ float row[128];
    __shared__ float l1s[128];
    __shared__ float l2s[8];
    const int g = blockIdx.x;
    const int j = threadIdx.x;

    row[j] = ps[(size_t)g * 128 + j];
    __syncthreads();

    float a = b1[j];
#pragma unroll 8
    for (int k = 0; k < 128; k++) a += row[k] * W1[j * 128 + k];
    a = fmaxf(a, 0.f);
    l1s[j] = a;
    lin1[(size_t)g * 128 + j] = a;
    lin1d[(size_t)g * 128 + j] = a;
    __syncthreads();

    if (j < 8) {
        float s = b2[j];
#pragma unroll 8
        for (int k = 0; k < 128; k++) s += l1s[k] * W2[j * 128 + k];
        lin2[(size_t)g * 8 + j] = s;
        l2s[j] = s;
    }
    __syncthreads();
    if (j == 0) {
        float mx = l2s[0];
#pragma unroll
        for (int q = 1; q < 8; q++) mx = fmaxf(mx, l2s[q]);
        float ex[8]; float sum = 0.f;
#pragma unroll
        for (int q = 0; q < 8; q++) { ex[q] = expf(l2s[q] - mx); sum += ex[q]; }
        float inv = 1.f / sum;
#pragma unroll
        for (int q = 0; q < 8; q++) soft[(size_t)g * 8 + q] = ex[q] * inv;
    }
}

extern "C" void kernel_launch(void* const* d_in, const int* in_sizes, int n_in,
                              void* d_out, int out_size)
{
    const float* x     = (const float*)d_in[0];
    const int*   ei    = (const int*)  d_in[1];
    const float* mask  = (const float*)d_in[2];
    const int*   batch = (const int*)  d_in[3];
    const float* eps   = (const float*)d_in[4];
    const float* Wf    = (const float*)d_in[5];
    const float* bf    = (const float*)d_in[6];
    const float* gW    = (const float*)d_in[7];   // [4][2][128][128]
    const float* gb    = (const float*)d_in[8];   // [4][2][128]
    const float* W1    = (const float*)d_in[9];
    const float* b1    = (const float*)d_in[10];
    const float* W2    = (const float*)d_in[11];
    const float* b2    = (const float*)d_in[12];

    float* out  = (float*)d_out;
    const size_t EMB = (size_t)NN * DH;
    float* embs = out;                       // [5][NN][128]
    float* ps   = out + 5 * EMB;             // [256][128]
    float* l1   = ps + (size_t)NG * DH;
    float* l1d  = l1 + (size_t)NG * DH;
    float* l2   = l1d + (size_t)NG * DH;
    float* sm   = l2 + (size_t)NG * DOUT;

    float *pooled = nullptr, *tmp = nullptr, *csr_mask = nullptr;
    int *deg = nullptr, *rowptr = nullptr, *cursor = nullptr, *bsums = nullptr, *csr_src = nullptr;
    cudaGetSymbolAddress((void**)&pooled,   g_pooled);
    cudaGetSymbolAddress((void**)&tmp,      g_tmp);
    cudaGetSymbolAddress((void**)&deg,      g_deg);
    cudaGetSymbolAddress((void**)&rowptr,   g_rowptr);
    cudaGetSymbolAddress((void**)&cursor,   g_cursor);
    cudaGetSymbolAddress((void**)&bsums,    g_bsums);
    cudaGetSymbolAddress((void**)&csr_src,  g_csr_src);
    cudaGetSymbolAddress((void**)&csr_mask, g_csr_mask);

    const int SMEM = (128 * 64 + 128 * 128) * (int)sizeof(float);  // 96 KB
    cudaFuncSetAttribute(gemm128<false>, cudaFuncAttributeMaxDynamicSharedMemorySize, SMEM);
    cudaFuncSetAttribute(gemm128<true>,  cudaFuncAttributeMaxDynamicSharedMemorySize, SMEM);

    const int GEMM_BLOCKS = (NN + 63) / 64;       // 1563
    const int SCAN_BLOCKS = (NN + SCAN_B - 1) / SCAN_B;  // 196
    const int EDGE_BLOCKS = (NE + 255) / 256;
    const int AGG_BLOCKS  = (NN * 32 + 255) / 256;
    const int POOL_BLOCKS = (NN + 127) / 128;

    // zero pooled_sum region (d_out is poisoned) + degree histogram
    cudaMemsetAsync(ps, 0, (size_t)NG * DH * sizeof(float), 0);
    cudaMemsetAsync(deg, 0, (size_t)NN * sizeof(int), 0);

    // CSR build (reused across all 4 layers)
    count_deg<<<EDGE_BLOCKS, 256>>>(ei, deg);
    scan1<<<SCAN_BLOCKS, SCAN_B>>>(deg, rowptr, bsums);
    scan2<<<1, 256>>>(bsums, SCAN_BLOCKS);
    scan3<<<SCAN_BLOCKS, SCAN_B>>>(rowptr, bsums, cursor);
    fill_csr<<<EDGE_BLOCKS, 256>>>(ei, mask, cursor, csr_src, csr_mask);

    // first linear (NO relu)
    gemm128<false><<<GEMM_BLOCKS, 256, SMEM>>>(x, Wf, bf, embs, NN);

    for (int l = 0; l < NLAYERS; l++) {
        const float* h = embs + (size_t)l * EMB;
        aggregate<<<AGG_BLOCKS, 256>>>(h, rowptr, csr_src, csr_mask, eps, l, pooled);
        gemm128<true><<<GEMM_BLOCKS, 256, SMEM>>>(
            pooled, gW + (size_t)(l * 2 + 0) * 128 * 128, gb + (size_t)(l * 2 + 0) * 128,
            tmp, NN);
        gemm128<true><<<GEMM_BLOCKS, 256, SMEM>>>(
            tmp, gW + (size_t)(l * 2 + 1) * 128 * 128, gb + (size_t)(l * 2 + 1) * 128,
            embs + (size_t)(l + 1) * EMB, NN);
    }

    pool_batch<<<POOL_BLOCKS, 128>>>(embs, batch, ps);
    head<<<NG, 128>>>(ps, W1, b1, W2, b2, l1, l1d, l2, sm);
}